// round 12
// baseline (speedup 1.0000x reference)
#include <cuda_runtime.h>
#include <cuda_bf16.h>
#include <cuda_fp16.h>
#include <cstdint>
#include <cstring>

#define Nn 1024
#define Mm 256
#define Bb 1024
#define Kk 1280
#define TMt 128           // CTA tile rows
#define TNt 64            // CTA tile cols
#define TKt 32            // K per staged tile
#define NTIL 40
#define BETA 0.01f
#define EPSL 1e-12f
#define THREADS 384       // 8 consumer warps + 4 producer warps
#define NCONS 256

typedef uint32_t u32;

// Fragment-packed plane layout (per k-tile), identical to R11:
//  A plane: [m16 tile 0..7][kstep 0..1][lane 0..31][16B]  = 8192 B
//  B plane: [n8-pair 0..3][kstep 0..1][lane 0..31][16B]   = 4096 B
#define APL 8192
#define BPL 4096
#define BUFSZ (6 * APL + 3 * BPL)    // 61440
#define SMTOT (2 * BUFSZ)            // 122880 B

// named barriers: FULL[buf] = 1+buf, EMPTY[buf] = 3+buf
static __device__ __forceinline__ void bar_sync(int id) {
    asm volatile("bar.sync %0, %1;" :: "r"(id), "r"(THREADS) : "memory");
}
static __device__ __forceinline__ void bar_arrive(int id) {
    asm volatile("bar.arrive %0, %1;" :: "r"(id), "r"(THREADS) : "memory");
}

static __device__ __forceinline__ void hilo16(float a, float b, u32& h, u32& l) {
    __half2 t = __floats2half2_rn(a, b);
    memcpy(&h, &t, 4);
    float fa = __half2float(__low2half(t));
    float fb = __half2float(__high2half(t));
    __half2 t2 = __floats2half2_rn(a - fa, b - fb);
    memcpy(&l, &t2, 4);
}
static __device__ __forceinline__ u32 pk16(float a, float b) {
    __half2 t = __floats2half2_rn(a, b);
    u32 h; memcpy(&h, &t, 4); return h;
}
static __device__ __forceinline__ u32 smem_u32(const void* p) {
    u32 a;
    asm("{ .reg .u64 t; cvta.to.shared.u64 t, %1; cvt.u32.u64 %0, t; }" : "=r"(a) : "l"(p));
    return a;
}
static __device__ __forceinline__ uint4 lds128(u32 addr) {
    uint4 r;
    asm volatile("ld.shared.v4.b32 {%0,%1,%2,%3}, [%4];"
                 : "=r"(r.x), "=r"(r.y), "=r"(r.z), "=r"(r.w) : "r"(addr));
    return r;
}
static __device__ __forceinline__ void mma16816(float* c, const uint4& a, u32 b0, u32 b1) {
    asm volatile(
        "mma.sync.aligned.m16n8k16.row.col.f32.f16.f16.f32 "
        "{%0,%1,%2,%3}, {%4,%5,%6,%7}, {%8,%9}, {%0,%1,%2,%3};"
        : "+f"(c[0]), "+f"(c[1]), "+f"(c[2]), "+f"(c[3])
        : "r"(a.x), "r"(a.y), "r"(a.z), "r"(a.w), "r"(b0), "r"(b1));
}

// STS offset for A value (n, kp): fp16x2 of k=2kp,2kp+1 at row n. (R11-proven)
static __device__ __forceinline__ u32 sts_off_a(int n, int kp) {
    int kpp = kp & 7;
    return (u32)((n >> 4) * 1024 + (kp >> 3) * 512 +
                 (((n & 7) * 4 + (kpp & 3)) * 16) +
                 (((kpp >= 4) ? 2 : 0) + ((n >> 3) & 1)) * 4);
}
// STS offset for B value (c, kp). (R11-proven)
static __device__ __forceinline__ u32 sts_off_b(int c, int kp) {
    int kpp = kp & 7;
    return (u32)((c >> 4) * 1024 + (kp >> 3) * 512 +
                 (((c & 7) * 4 + (kpp & 3)) * 16) +
                 ((((c >> 3) & 1) * 2) + ((kpp >= 4) ? 1 : 0)) * 4);
}

// z = softthresh(W1 @ x + W2 @ y); W1[n,k]=v[N-1+n-k].
// fp16 split-2 A + fp16 B, Gauss 3-product; warp-specialized producer/consumer.
__global__ __launch_bounds__(THREADS, 1)
void toeplitz_hmma6_kernel(
    const float* __restrict__ v_re,  const float* __restrict__ v_im,
    const float* __restrict__ W2_re, const float* __restrict__ W2_im,
    const float* __restrict__ x_re,  const float* __restrict__ x_im,
    const float* __restrict__ y_re,  const float* __restrict__ y_im,
    void* __restrict__ out, int omode)
{
    extern __shared__ char smem[];
    const u32 smb = smem_u32(smem);
    const int tid = threadIdx.x;
    const int wid = tid >> 5;
    const int row0 = blockIdx.y * TMt;
    const int col0 = blockIdx.x * TNt;

    if (wid >= 8) {
        // ================= PRODUCER (warps 8-11, 128 threads) =================
        const int pt = tid - NCONS;   // 0..127
        // tile-invariant STS offsets: A 16 entries, B 8 entries per thread
        u32 offA[16], offB[8];
        #pragma unroll
        for (int it = 0; it < 16; ++it) {
            int idx = pt + it * 128;              // 0..2047
            offA[it] = sts_off_a(idx >> 4, idx & 15);
        }
        #pragma unroll
        for (int it = 0; it < 8; ++it) {
            int idx = pt + it * 128;              // 0..1023
            offB[it] = sts_off_b(idx & 63, idx >> 6);
        }

        for (int t = 0; t < NTIL; ++t) {
            const int buf = t & 1;
            if (t >= 2) bar_sync(3 + buf);        // wait consumers done with buf
            char* base = smem + buf * BUFSZ;
            const int k0 = t * TKt;

            if (k0 < Nn) {
                #pragma unroll
                for (int it = 0; it < 16; ++it) {
                    int idx = pt + it * 128;
                    int kp = idx & 15, n = idx >> 4;
                    int g = 1023 + (row0 + n) - (k0 + 2 * kp);
                    float r0 = v_re[g], r1 = v_re[g - 1];
                    float i0 = v_im[g], i1 = v_im[g - 1];
                    const u32 o = offA[it];
                    u32 h, l;
                    hilo16(r0, r1, h, l);
                    *(u32*)(base + o) = h; *(u32*)(base + APL + o) = l;
                    hilo16(i0, i1, h, l);
                    *(u32*)(base + 2 * APL + o) = h; *(u32*)(base + 3 * APL + o) = l;
                    hilo16(r0 + i0, r1 + i1, h, l);
                    *(u32*)(base + 4 * APL + o) = h; *(u32*)(base + 5 * APL + o) = l;
                }
            } else {
                #pragma unroll
                for (int it = 0; it < 16; ++it) {
                    int idx = pt + it * 128;
                    int kp = idx & 15, n = idx >> 4;
                    int g = (row0 + n) * Mm + (k0 - Nn + 2 * kp);
                    float r0 = W2_re[g], r1 = W2_re[g + 1];
                    float i0 = W2_im[g], i1 = W2_im[g + 1];
                    const u32 o = offA[it];
                    u32 h, l;
                    hilo16(r0, r1, h, l);
                    *(u32*)(base + o) = h; *(u32*)(base + APL + o) = l;
                    hilo16(i0, i1, h, l);
                    *(u32*)(base + 2 * APL + o) = h; *(u32*)(base + 3 * APL + o) = l;
                    hilo16(r0 + i0, r1 + i1, h, l);
                    *(u32*)(base + 4 * APL + o) = h; *(u32*)(base + 5 * APL + o) = l;
                }
            }
            {
                const float* sr = (k0 < Nn) ? x_re : y_re;
                const float* si = (k0 < Nn) ? x_im : y_im;
                const int kb = (k0 < Nn) ? k0 : (k0 - Nn);
                char* Bb0 = base + 6 * APL;
                #pragma unroll
                for (int it = 0; it < 8; ++it) {
                    int idx = pt + it * 128;
                    int cc = idx & 63, kp = idx >> 6;
                    int g = (kb + 2 * kp) * Bb + col0 + cc;
                    float r0 = sr[g], r1 = sr[g + Bb];
                    float i0 = si[g], i1 = si[g + Bb];
                    const u32 o = offB[it];
                    *(u32*)(Bb0 + o)           = pk16(r0, r1);
                    *(u32*)(Bb0 + BPL + o)     = pk16(i0, i1);
                    *(u32*)(Bb0 + 2 * BPL + o) = pk16(r0 + i0, r1 + i1);
                }
            }
            bar_sync(1 + buf);   // publish buf (bar.sync fences + drains STS)
        }
        return;
    }

    // ================= CONSUMER (warps 0-7) =================
    const int lid = tid & 31;
    const int wr = wid >> 1, wc = wid & 1;    // 4x2 warp grid, warp tile 32x32
    const int r4 = lid >> 2;
    const int c2 = (lid & 3) * 2;
    const u32 lane16 = (u32)(lid * 16);

    float acc[3][2][4][4];   // [plane][mt][nt][quad]
    #pragma unroll
    for (int p = 0; p < 3; ++p)
        #pragma unroll
        for (int mt = 0; mt < 2; ++mt)
            #pragma unroll
            for (int nt = 0; nt < 4; ++nt)
                #pragma unroll
                for (int q = 0; q < 4; ++q) acc[p][mt][nt][q] = 0.0f;

    for (int t = 0; t < NTIL; ++t) {
        const int buf = t & 1;
        bar_sync(1 + buf);                     // wait buf full
        const u32 base = smb + buf * BUFSZ;
        #pragma unroll
        for (int ks = 0; ks < 2; ++ks) {
            const u32 ko = (u32)(ks * 512) + lane16;
            #pragma unroll
            for (int p = 0; p < 3; ++p) {
                const u32 Ah = base + (2 * p) * APL;
                const u32 Al = Ah + APL;
                const u32 Bh = base + 6 * APL + p * BPL;
                uint4 ah0 = lds128(Ah + (u32)((wr * 2) * 1024) + ko);
                uint4 ah1 = lds128(Ah + (u32)((wr * 2 + 1) * 1024) + ko);
                uint4 al0 = lds128(Al + (u32)((wr * 2) * 1024) + ko);
                uint4 al1 = lds128(Al + (u32)((wr * 2 + 1) * 1024) + ko);
                uint4 bh0 = lds128(Bh + (u32)((wc * 2) * 1024) + ko);
                uint4 bh1 = lds128(Bh + (u32)((wc * 2 + 1) * 1024) + ko);
                #pragma unroll
                for (int mt = 0; mt < 2; ++mt) {
                    const uint4& ah = mt ? ah1 : ah0;
                    const uint4& al = mt ? al1 : al0;
                    mma16816(acc[p][mt][0], ah, bh0.x, bh0.y);
                    mma16816(acc[p][mt][0], al, bh0.x, bh0.y);
                    mma16816(acc[p][mt][1], ah, bh0.z, bh0.w);
                    mma16816(acc[p][mt][1], al, bh0.z, bh0.w);
                    mma16816(acc[p][mt][2], ah, bh1.x, bh1.y);
                    mma16816(acc[p][mt][2], al, bh1.x, bh1.y);
                    mma16816(acc[p][mt][3], ah, bh1.z, bh1.w);
                    mma16816(acc[p][mt][3], al, bh1.z, bh1.w);
                }
            }
        }
        bar_arrive(3 + buf);                   // release buf for producer
    }

    // ---- epilogue: re = P1-P2, im = P3-P1-P2, soft-threshold, store ----
    const int wm = wr * 32, wn = wc * 32;
    #pragma unroll
    for (int mt = 0; mt < 2; ++mt) {
        #pragma unroll
        for (int nt = 0; nt < 4; ++nt) {
            #pragma unroll
            for (int half = 0; half < 2; ++half) {
                const int q0 = half * 2;
                const int row = row0 + wm + mt * 16 + r4 + half * 8;
                const int col = col0 + wn + nt * 8 + c2;
                float p1a = acc[0][mt][nt][q0],     p1b = acc[0][mt][nt][q0 + 1];
                float p2a = acc[1][mt][nt][q0],     p2b = acc[1][mt][nt][q0 + 1];
                float p3a = acc[2][mt][nt][q0],     p3b = acc[2][mt][nt][q0 + 1];
                float rea = p1a - p2a,  reb = p1b - p2b;
                float ima = p3a - p1a - p2a, imb = p3b - p1b - p2b;
                float maga = sqrtf(rea * rea + ima * ima);
                float sca  = fmaxf(maga - BETA, 0.0f) / fmaxf(maga, EPSL);
                float magb = sqrtf(reb * reb + imb * imb);
                float scb  = fmaxf(magb - BETA, 0.0f) / fmaxf(magb, EPSL);
                rea *= sca; ima *= sca; reb *= scb; imb *= scb;
                const int e = row * Bb + col;
                if (omode == 0) {
                    __nv_bfloat162 pa = __floats2bfloat162_rn(rea, ima);
                    __nv_bfloat162 pb = __floats2bfloat162_rn(reb, imb);
                    u32 ua, ub; memcpy(&ua, &pa, 4); memcpy(&ub, &pb, 4);
                    *(uint2*)((u32*)out + e) = make_uint2(ua, ub);
                } else {
                    *(float2*)((float*)out + e) = make_float2(rea, reb);
                }
            }
        }
    }
}

extern "C" void kernel_launch(void* const* d_in, const int* in_sizes, int n_in,
                              void* d_out, int out_size) {
    // Crash-proof input dispatch: classify by element count (elements or bytes).
    int scale = 1;
    bool have2047 = false, have8188 = false;
    for (int i = 0; i < n_in && i < 8; ++i) {
        if (in_sizes[i] == 2 * Nn - 1) have2047 = true;
        if (in_sizes[i] == (2 * Nn - 1) * 4) have8188 = true;
    }
    if (!have2047 && have8188) scale = 4;

    const float* vp[2] = {0, 0};
    const float* xp[2] = {0, 0};
    const float* mp[4] = {0, 0, 0, 0};
    int nv = 0, nx = 0, nm = 0;
    for (int i = 0; i < n_in && i < 8; ++i) {
        const float* p = (const float*)d_in[i];
        long s = in_sizes[i];
        if (s == (long)(2 * Nn - 1) * scale)      { if (nv < 2) vp[nv++] = p; }
        else if (s == (long)Nn * Bb * scale)      { if (nx < 2) xp[nx++] = p; }
        else if (s == (long)Nn * Mm * scale)      { if (nm < 4) mp[nm++] = p; }
    }
    const float* v_re  = vp[0] ? vp[0] : (const float*)d_in[0];
    const float* v_im  = vp[1] ? vp[1] : (const float*)d_in[1];
    const float* W2_re = mp[0] ? mp[0] : (const float*)d_in[2];
    const float* W2_im = mp[1] ? mp[1] : (const float*)d_in[3];
    const float* x_re  = xp[0] ? xp[0] : (const float*)d_in[4];
    const float* x_im  = xp[1] ? xp[1] : (const float*)d_in[5];
    const float* y_re  = mp[2] ? mp[2] : (const float*)d_in[6];
    const float* y_im  = mp[3] ? mp[3] : (const float*)d_in[7];

    const int omode = (out_size >= 2 * Nn * Bb) ? 0 : 1;

    cudaFuncSetAttribute(toeplitz_hmma6_kernel,
                         cudaFuncAttributeMaxDynamicSharedMemorySize, SMTOT);
    dim3 grid(Bb / TNt, Nn / TMt);   // (16, 8) = 128 CTAs
    toeplitz_hmma6_kernel<<<grid, THREADS, SMTOT>>>(
        v_re, v_im, W2_re, W2_im, x_re, x_im, y_re, y_im,
        d_out, omode);
}

// round 13
// speedup vs baseline: 1.2170x; 1.2170x over previous
#include <cuda_runtime.h>
#include <cuda_bf16.h>
#include <cuda_fp16.h>
#include <cstdint>
#include <cstring>

#define Nn 1024
#define Mm 256
#define Bb 1024
#define Kk 1280
#define TMt 128           // CTA tile rows
#define TNt 64            // CTA tile cols
#define TKt 32            // K per staged tile
#define NTIL 40           // 8 W2 tiles then 32 Toeplitz tiles
#define BETA 0.01f
#define EPSL 1e-12f
#define THREADS 256

typedef uint32_t u32;

// A ring: 16 m16-slots. Slot = 6 planes (rh,rl,ih,il,sh,sl) x [ks 0..1][lane][16B]
//   slot stride 6144, plane stride 1024, ks stride 512.
// B: double buffer, 3 planes (rh,ih,sh) x [n8-pair 0..3][ks][lane][16B], plane 4096.
#define SLOT 6144
#define RINGB (16 * SLOT)          // 98304
#define BBUF 12288
#define SMTOT (RINGB + 2 * BBUF)   // 122880

static __device__ __forceinline__ void hilo16(float a, float b, u32& h, u32& l) {
    __half2 t = __floats2half2_rn(a, b);
    memcpy(&h, &t, 4);
    float fa = __half2float(__low2half(t));
    float fb = __half2float(__high2half(t));
    __half2 t2 = __floats2half2_rn(a - fa, b - fb);
    memcpy(&l, &t2, 4);
}
static __device__ __forceinline__ u32 pk16(float a, float b) {
    __half2 t = __floats2half2_rn(a, b);
    u32 h; memcpy(&h, &t, 4); return h;
}
static __device__ __forceinline__ u32 smem_u32(const void* p) {
    u32 a;
    asm("{ .reg .u64 t; cvta.to.shared.u64 t, %1; cvt.u32.u64 %0, t; }" : "=r"(a) : "l"(p));
    return a;
}
static __device__ __forceinline__ uint4 lds128(u32 addr) {
    uint4 r;
    asm volatile("ld.shared.v4.b32 {%0,%1,%2,%3}, [%4];"
                 : "=r"(r.x), "=r"(r.y), "=r"(r.z), "=r"(r.w) : "r"(addr));
    return r;
}
static __device__ __forceinline__ void mma16816(float* c, const uint4& a, u32 b0, u32 b1) {
    asm volatile(
        "mma.sync.aligned.m16n8k16.row.col.f32.f16.f16.f32 "
        "{%0,%1,%2,%3}, {%4,%5,%6,%7}, {%8,%9}, {%0,%1,%2,%3};"
        : "+f"(c[0]), "+f"(c[1]), "+f"(c[2]), "+f"(c[3])
        : "r"(a.x), "r"(a.y), "r"(a.z), "r"(a.w), "r"(b0), "r"(b1));
}

// k0 of schedule index i: W2 region first (i<8), then Toeplitz ascending.
static __device__ __forceinline__ int k0_of(int i) {
    return (i < 8) ? (1024 + i * 32) : ((i - 8) * 32);
}
// ring slot of m16-tile j for schedule index i
static __device__ __forceinline__ int slot_of(int i, int j) {
    return (i < 8) ? (8 * (i & 1) + j) : ((j - 2 * (i - 8)) & 15);
}
// within-(slot,plane) offset for value (nl in 0..15, kp in 0..15)  [R11-proven map]
static __device__ __forceinline__ u32 inner_a(int nl, int kp) {
    int kpp = kp & 7;
    return (u32)((kp >> 3) * 512 + (((nl & 7) * 4 + (kpp & 3)) * 16) +
                 (((kpp >= 4) ? 2 : 0) + (nl >> 3)) * 4);
}
// within-plane offset for B value (c in 0..63, kp in 0..15)  [R11-proven map]
static __device__ __forceinline__ u32 off_b(int c, int kp) {
    int kpp = kp & 7;
    return (u32)((c >> 4) * 1024 + (kp >> 3) * 512 +
                 (((c & 7) * 4 + (kpp & 3)) * 16) +
                 ((((c >> 3) & 1) * 2) + ((kpp >= 4) ? 1 : 0)) * 4);
}

// z = softthresh(W1 @ x + W2 @ y); W1[n,k]=v[N-1+n-k].
// fp16 split-2 A + fp16 B, Gauss 3-product; Toeplitz A-plane ring (4x less A staging).
__global__ __launch_bounds__(THREADS, 1)
void toeplitz_hmma7_kernel(
    const float* __restrict__ v_re,  const float* __restrict__ v_im,
    const float* __restrict__ W2_re, const float* __restrict__ W2_im,
    const float* __restrict__ x_re,  const float* __restrict__ x_im,
    const float* __restrict__ y_re,  const float* __restrict__ y_im,
    void* __restrict__ out, int omode)
{
    extern __shared__ char smem[];
    const u32 smb = smem_u32(smem);
    const int tid = threadIdx.x;
    const int wid = tid >> 5;
    const int lid = tid & 31;
    const int wr = wid >> 1, wc = wid & 1;    // 4x2 warp grid, warp tile 32x32
    const int r4 = lid >> 2;
    const int c2 = (lid & 3) * 2;
    const int row0 = blockIdx.y * TMt;
    const int col0 = blockIdx.x * TNt;
    const u32 lane16 = (u32)(lid * 16);

    float acc[3][2][4][4];
    #pragma unroll
    for (int p = 0; p < 3; ++p)
        #pragma unroll
        for (int mt = 0; mt < 2; ++mt)
            #pragma unroll
            for (int nt = 0; nt < 4; ++nt)
                #pragma unroll
                for (int q = 0; q < 4; ++q) acc[p][mt][nt][q] = 0.0f;

    // staging regs: full-A uses 8 slots of regs; incremental uses 2.
    float Ar0[8], Ar1[8], Ai0[8], Ai1[8];
    float Br0[4], Br1[4], Bi0[4], Bi1[4];

    auto load_regs = [&](int i) {
        const int k0 = k0_of(i);
        const bool fullA = (i < 8) || (i == 8);
        if (fullA) {
            if (i < 8) {
                #pragma unroll
                for (int it = 0; it < 8; ++it) {
                    int idx = tid + it * THREADS;     // 0..2047
                    int kp = idx & 15, n = idx >> 4;
                    int g = (row0 + n) * Mm + (k0 - Nn + 2 * kp);
                    Ar0[it] = W2_re[g]; Ar1[it] = W2_re[g + 1];
                    Ai0[it] = W2_im[g]; Ai1[it] = W2_im[g + 1];
                }
            } else {
                #pragma unroll
                for (int it = 0; it < 8; ++it) {
                    int idx = tid + it * THREADS;
                    int kp = idx & 15, n = idx >> 4;
                    int g = 1023 + (row0 + n) - (k0 + 2 * kp);
                    Ar0[it] = v_re[g]; Ar1[it] = v_re[g - 1];
                    Ai0[it] = v_im[g]; Ai1[it] = v_im[g - 1];
                }
            }
        } else {
            // incremental: only rows n = 0..31 are new
            #pragma unroll
            for (int it = 0; it < 2; ++it) {
                int idx = tid + it * THREADS;         // 0..511
                int kp = idx & 15, n = idx >> 4;      // n in 0..31
                int g = 1023 + (row0 + n) - (k0 + 2 * kp);
                Ar0[it] = v_re[g]; Ar1[it] = v_re[g - 1];
                Ai0[it] = v_im[g]; Ai1[it] = v_im[g - 1];
            }
        }
        const float* sr = (k0 < Nn) ? x_re : y_re;
        const float* si = (k0 < Nn) ? x_im : y_im;
        const int kb = (k0 < Nn) ? k0 : (k0 - Nn);
        #pragma unroll
        for (int it = 0; it < 4; ++it) {
            int idx = tid + it * THREADS;             // 0..1023
            int cc = idx & 63, kp = idx >> 6;
            int g = (kb + 2 * kp) * Bb + col0 + cc;
            Br0[it] = sr[g]; Br1[it] = sr[g + Bb];
            Bi0[it] = si[g]; Bi1[it] = si[g + Bb];
        }
    };

    auto store_A_item = [&](int i, int it, int idx) {
        int kp = idx & 15, n = idx >> 4;
        char* sb = smem + slot_of(i, n >> 4) * SLOT;
        const u32 o = inner_a(n & 15, kp);
        u32 h, l;
        hilo16(Ar0[it], Ar1[it], h, l);
        *(u32*)(sb + o) = h;            *(u32*)(sb + 1024 + o) = l;
        hilo16(Ai0[it], Ai1[it], h, l);
        *(u32*)(sb + 2048 + o) = h;     *(u32*)(sb + 3072 + o) = l;
        hilo16(Ar0[it] + Ai0[it], Ar1[it] + Ai1[it], h, l);
        *(u32*)(sb + 4096 + o) = h;     *(u32*)(sb + 5120 + o) = l;
    };

    auto store_smem = [&](int i) {
        const bool fullA = (i < 8) || (i == 8);
        if (fullA) {
            #pragma unroll
            for (int it = 0; it < 8; ++it) store_A_item(i, it, tid + it * THREADS);
        } else {
            #pragma unroll
            for (int it = 0; it < 2; ++it) store_A_item(i, it, tid + it * THREADS);
        }
        char* Bp = smem + RINGB + (i & 1) * BBUF;
        #pragma unroll
        for (int it = 0; it < 4; ++it) {
            int idx = tid + it * THREADS;
            const u32 o = off_b(idx & 63, idx >> 6);
            *(u32*)(Bp + o)        = pk16(Br0[it], Br1[it]);
            *(u32*)(Bp + 4096 + o) = pk16(Bi0[it], Bi1[it]);
            *(u32*)(Bp + 8192 + o) = pk16(Br0[it] + Bi0[it], Br1[it] + Bi1[it]);
        }
    };

    load_regs(0);
    store_smem(0);
    __syncthreads();

    for (int i = 0; i < NTIL; ++i) {
        if (i + 1 < NTIL) load_regs(i + 1);

        const u32 s0 = smb + (u32)(slot_of(i, wr * 2) * SLOT);
        const u32 s1 = smb + (u32)(slot_of(i, wr * 2 + 1) * SLOT);
        const u32 bb = smb + RINGB + (u32)((i & 1) * BBUF);
        #pragma unroll
        for (int ks = 0; ks < 2; ++ks) {
            const u32 ko = (u32)(ks * 512) + lane16;
            #pragma unroll
            for (int p = 0; p < 3; ++p) {
                const u32 ah_o = (u32)(2 * p * 1024) + ko;
                const u32 bo   = (u32)(p * 4096) + ko;
                uint4 ah0 = lds128(s0 + ah_o);
                uint4 ah1 = lds128(s1 + ah_o);
                uint4 al0 = lds128(s0 + ah_o + 1024);
                uint4 al1 = lds128(s1 + ah_o + 1024);
                uint4 bh0 = lds128(bb + bo + (u32)((wc * 2) * 1024));
                uint4 bh1 = lds128(bb + bo + (u32)((wc * 2 + 1) * 1024));
                #pragma unroll
                for (int mt = 0; mt < 2; ++mt) {
                    const uint4& ah = mt ? ah1 : ah0;
                    const uint4& al = mt ? al1 : al0;
                    mma16816(acc[p][mt][0], ah, bh0.x, bh0.y);
                    mma16816(acc[p][mt][0], al, bh0.x, bh0.y);
                    mma16816(acc[p][mt][1], ah, bh0.z, bh0.w);
                    mma16816(acc[p][mt][1], al, bh0.z, bh0.w);
                    mma16816(acc[p][mt][2], ah, bh1.x, bh1.y);
                    mma16816(acc[p][mt][2], al, bh1.x, bh1.y);
                    mma16816(acc[p][mt][3], ah, bh1.z, bh1.w);
                    mma16816(acc[p][mt][3], al, bh1.z, bh1.w);
                }
            }
        }

        if (i + 1 < NTIL) store_smem(i + 1);
        __syncthreads();
    }

    // ---- epilogue: re = P1-P2, im = P3-P1-P2, soft-threshold, store ----
    const int wm = wr * 32, wn = wc * 32;
    #pragma unroll
    for (int mt = 0; mt < 2; ++mt) {
        #pragma unroll
        for (int nt = 0; nt < 4; ++nt) {
            #pragma unroll
            for (int half = 0; half < 2; ++half) {
                const int q0 = half * 2;
                const int row = row0 + wm + mt * 16 + r4 + half * 8;
                const int col = col0 + wn + nt * 8 + c2;
                float p1a = acc[0][mt][nt][q0],     p1b = acc[0][mt][nt][q0 + 1];
                float p2a = acc[1][mt][nt][q0],     p2b = acc[1][mt][nt][q0 + 1];
                float p3a = acc[2][mt][nt][q0],     p3b = acc[2][mt][nt][q0 + 1];
                float rea = p1a - p2a,  reb = p1b - p2b;
                float ima = p3a - p1a - p2a, imb = p3b - p1b - p2b;
                float maga = sqrtf(rea * rea + ima * ima);
                float sca  = fmaxf(maga - BETA, 0.0f) / fmaxf(maga, EPSL);
                float magb = sqrtf(reb * reb + imb * imb);
                float scb  = fmaxf(magb - BETA, 0.0f) / fmaxf(magb, EPSL);
                rea *= sca; ima *= sca; reb *= scb; imb *= scb;
                const int e = row * Bb + col;
                if (omode == 0) {
                    __nv_bfloat162 pa = __floats2bfloat162_rn(rea, ima);
                    __nv_bfloat162 pb = __floats2bfloat162_rn(reb, imb);
                    u32 ua, ub; memcpy(&ua, &pa, 4); memcpy(&ub, &pb, 4);
                    *(uint2*)((u32*)out + e) = make_uint2(ua, ub);
                } else {
                    *(float2*)((float*)out + e) = make_float2(rea, reb);
                }
            }
        }
    }
}

extern "C" void kernel_launch(void* const* d_in, const int* in_sizes, int n_in,
                              void* d_out, int out_size) {
    // Crash-proof input dispatch: classify by element count (elements or bytes).
    int scale = 1;
    bool have2047 = false, have8188 = false;
    for (int i = 0; i < n_in && i < 8; ++i) {
        if (in_sizes[i] == 2 * Nn - 1) have2047 = true;
        if (in_sizes[i] == (2 * Nn - 1) * 4) have8188 = true;
    }
    if (!have2047 && have8188) scale = 4;

    const float* vp[2] = {0, 0};
    const float* xp[2] = {0, 0};
    const float* mp[4] = {0, 0, 0, 0};
    int nv = 0, nx = 0, nm = 0;
    for (int i = 0; i < n_in && i < 8; ++i) {
        const float* p = (const float*)d_in[i];
        long s = in_sizes[i];
        if (s == (long)(2 * Nn - 1) * scale)      { if (nv < 2) vp[nv++] = p; }
        else if (s == (long)Nn * Bb * scale)      { if (nx < 2) xp[nx++] = p; }
        else if (s == (long)Nn * Mm * scale)      { if (nm < 4) mp[nm++] = p; }
    }
    const float* v_re  = vp[0] ? vp[0] : (const float*)d_in[0];
    const float* v_im  = vp[1] ? vp[1] : (const float*)d_in[1];
    const float* W2_re = mp[0] ? mp[0] : (const float*)d_in[2];
    const float* W2_im = mp[1] ? mp[1] : (const float*)d_in[3];
    const float* x_re  = xp[0] ? xp[0] : (const float*)d_in[4];
    const float* x_im  = xp[1] ? xp[1] : (const float*)d_in[5];
    const float* y_re  = mp[2] ? mp[2] : (const float*)d_in[6];
    const float* y_im  = mp[3] ? mp[3] : (const float*)d_in[7];

    const int omode = (out_size >= 2 * Nn * Bb) ? 0 : 1;

    cudaFuncSetAttribute(toeplitz_hmma7_kernel,
                         cudaFuncAttributeMaxDynamicSharedMemorySize, SMTOT);
    dim3 grid(Bb / TNt, Nn / TMt);   // (16, 8) = 128 CTAs
    toeplitz_hmma7_kernel<<<grid, THREADS, SMTOT>>>(
        v_re, v_im, W2_re, W2_im, x_re, x_im, y_re, y_im,
        d_out, omode);
}

// round 14
// speedup vs baseline: 1.3182x; 1.0832x over previous
#include <cuda_runtime.h>
#include <cuda_bf16.h>
#include <cuda_fp16.h>
#include <cstdint>
#include <cstring>

#define Nn 1024
#define Mm 256
#define Bb 1024
#define Kk 1280
#define TMt 128           // CTA tile rows
#define TNt 64            // CTA tile cols
#define TKt 32            // K per staged tile
#define NTIL 40           // 8 W2 tiles then 32 Toeplitz tiles
#define BETA 0.01f
#define EPSL 1e-12f
#define THREADS 256

typedef uint32_t u32;

// A ring: 16 m16-slots. Slot = 4 planes (rh,rl,ih,il) x [ks 0..1][lane][16B]
//   slot stride 4096, plane stride 1024, ks stride 512.
// B: double buffer, 2 planes (rh,ih) x [n8-pair 0..3][ks][lane][16B], plane 4096.
// s-planes (r+i) are reconstructed in consumer registers (fast2sum).
#define SLOT 4096
#define RINGB (16 * SLOT)          // 65536
#define BBUF 8192
#define SMTOT (RINGB + 2 * BBUF)   // 81920

static __device__ __forceinline__ void hilo16(float a, float b, u32& h, u32& l) {
    __half2 t = __floats2half2_rn(a, b);
    memcpy(&h, &t, 4);
    float fa = __half2float(__low2half(t));
    float fb = __half2float(__high2half(t));
    __half2 t2 = __floats2half2_rn(a - fa, b - fb);
    memcpy(&l, &t2, 4);
}
static __device__ __forceinline__ u32 pk16(float a, float b) {
    __half2 t = __floats2half2_rn(a, b);
    u32 h; memcpy(&h, &t, 4); return h;
}
static __device__ __forceinline__ u32 h2add(u32 a, u32 b) {
    __half2 x, y; memcpy(&x, &a, 4); memcpy(&y, &b, 4);
    __half2 r = __hadd2(x, y); u32 d; memcpy(&d, &r, 4); return d;
}
static __device__ __forceinline__ u32 h2sub(u32 a, u32 b) {
    __half2 x, y; memcpy(&x, &a, 4); memcpy(&y, &b, 4);
    __half2 r = __hsub2(x, y); u32 d; memcpy(&d, &r, 4); return d;
}
// fast2sum: s = rh+ih (rounded), compensation e = ih-(s-rh); sl = (rl+il)+e
static __device__ __forceinline__ void s2(u32 rh, u32 rl, u32 ih, u32 il,
                                          u32& sh, u32& sl) {
    sh = h2add(rh, ih);
    u32 e = h2sub(ih, h2sub(sh, rh));
    sl = h2add(h2add(rl, il), e);
}
static __device__ __forceinline__ void s2v(const uint4& rh, const uint4& rl,
                                           const uint4& ih, const uint4& il,
                                           uint4& sh, uint4& sl) {
    s2(rh.x, rl.x, ih.x, il.x, sh.x, sl.x);
    s2(rh.y, rl.y, ih.y, il.y, sh.y, sl.y);
    s2(rh.z, rl.z, ih.z, il.z, sh.z, sl.z);
    s2(rh.w, rl.w, ih.w, il.w, sh.w, sl.w);
}
static __device__ __forceinline__ u32 smem_u32(const void* p) {
    u32 a;
    asm("{ .reg .u64 t; cvta.to.shared.u64 t, %1; cvt.u32.u64 %0, t; }" : "=r"(a) : "l"(p));
    return a;
}
static __device__ __forceinline__ uint4 lds128(u32 addr) {
    uint4 r;
    asm volatile("ld.shared.v4.b32 {%0,%1,%2,%3}, [%4];"
                 : "=r"(r.x), "=r"(r.y), "=r"(r.z), "=r"(r.w) : "r"(addr));
    return r;
}
static __device__ __forceinline__ void mma16816(float* c, const uint4& a, u32 b0, u32 b1) {
    asm volatile(
        "mma.sync.aligned.m16n8k16.row.col.f32.f16.f16.f32 "
        "{%0,%1,%2,%3}, {%4,%5,%6,%7}, {%8,%9}, {%0,%1,%2,%3};"
        : "+f"(c[0]), "+f"(c[1]), "+f"(c[2]), "+f"(c[3])
        : "r"(a.x), "r"(a.y), "r"(a.z), "r"(a.w), "r"(b0), "r"(b1));
}

// k0 of schedule index i: W2 region first (i<8), then Toeplitz ascending.
static __device__ __forceinline__ int k0_of(int i) {
    return (i < 8) ? (1024 + i * 32) : ((i - 8) * 32);
}
// ring slot of m16-tile j for schedule index i
static __device__ __forceinline__ int slot_of(int i, int j) {
    return (i < 8) ? (8 * (i & 1) + j) : ((j - 2 * (i - 8)) & 15);
}
// within-(slot,plane) offset for value (nl in 0..15, kp in 0..15)  [R11-proven map]
static __device__ __forceinline__ u32 inner_a(int nl, int kp) {
    int kpp = kp & 7;
    return (u32)((kp >> 3) * 512 + (((nl & 7) * 4 + (kpp & 3)) * 16) +
                 (((kpp >= 4) ? 2 : 0) + (nl >> 3)) * 4);
}
// within-plane offset for B value (c in 0..63, kp in 0..15)  [R11-proven map]
static __device__ __forceinline__ u32 off_b(int c, int kp) {
    int kpp = kp & 7;
    return (u32)((c >> 4) * 1024 + (kp >> 3) * 512 +
                 (((c & 7) * 4 + (kpp & 3)) * 16) +
                 ((((c >> 3) & 1) * 2) + ((kpp >= 4) ? 1 : 0)) * 4);
}

// z = softthresh(W1 @ x + W2 @ y); W1[n,k]=v[N-1+n-k].
// fp16 split-2 + Gauss; A-ring; s-planes computed in registers (no smem).
__global__ __launch_bounds__(THREADS, 1)
void toeplitz_hmma8_kernel(
    const float* __restrict__ v_re,  const float* __restrict__ v_im,
    const float* __restrict__ W2_re, const float* __restrict__ W2_im,
    const float* __restrict__ x_re,  const float* __restrict__ x_im,
    const float* __restrict__ y_re,  const float* __restrict__ y_im,
    void* __restrict__ out, int omode)
{
    extern __shared__ char smem[];
    const u32 smb = smem_u32(smem);
    const int tid = threadIdx.x;
    const int wid = tid >> 5;
    const int lid = tid & 31;
    const int wr = wid >> 1, wc = wid & 1;    // 4x2 warp grid, warp tile 32x32
    const int r4 = lid >> 2;
    const int c2 = (lid & 3) * 2;
    const int row0 = blockIdx.y * TMt;
    const int col0 = blockIdx.x * TNt;
    const u32 lane16 = (u32)(lid * 16);

    float acc[3][2][4][4];
    #pragma unroll
    for (int p = 0; p < 3; ++p)
        #pragma unroll
        for (int mt = 0; mt < 2; ++mt)
            #pragma unroll
            for (int nt = 0; nt < 4; ++nt)
                #pragma unroll
                for (int q = 0; q < 4; ++q) acc[p][mt][nt][q] = 0.0f;

    float Ar0[8], Ar1[8], Ai0[8], Ai1[8];
    float Br0[4], Br1[4], Bi0[4], Bi1[4];

    auto load_regs = [&](int i) {
        const int k0 = k0_of(i);
        const bool fullA = (i <= 8);
        if (fullA) {
            if (i < 8) {
                #pragma unroll
                for (int it = 0; it < 8; ++it) {
                    int idx = tid + it * THREADS;     // 0..2047
                    int kp = idx & 15, n = idx >> 4;
                    int g = (row0 + n) * Mm + (k0 - Nn + 2 * kp);
                    Ar0[it] = W2_re[g]; Ar1[it] = W2_re[g + 1];
                    Ai0[it] = W2_im[g]; Ai1[it] = W2_im[g + 1];
                }
            } else {
                #pragma unroll
                for (int it = 0; it < 8; ++it) {
                    int idx = tid + it * THREADS;
                    int kp = idx & 15, n = idx >> 4;
                    int g = 1023 + (row0 + n) - (k0 + 2 * kp);
                    Ar0[it] = v_re[g]; Ar1[it] = v_re[g - 1];
                    Ai0[it] = v_im[g]; Ai1[it] = v_im[g - 1];
                }
            }
        } else {
            #pragma unroll
            for (int it = 0; it < 2; ++it) {
                int idx = tid + it * THREADS;         // 0..511, n in 0..31
                int kp = idx & 15, n = idx >> 4;
                int g = 1023 + (row0 + n) - (k0 + 2 * kp);
                Ar0[it] = v_re[g]; Ar1[it] = v_re[g - 1];
                Ai0[it] = v_im[g]; Ai1[it] = v_im[g - 1];
            }
        }
        const float* sr = (k0 < Nn) ? x_re : y_re;
        const float* si = (k0 < Nn) ? x_im : y_im;
        const int kb = (k0 < Nn) ? k0 : (k0 - Nn);
        #pragma unroll
        for (int it = 0; it < 4; ++it) {
            int idx = tid + it * THREADS;             // 0..1023
            int cc = idx & 63, kp = idx >> 6;
            int g = (kb + 2 * kp) * Bb + col0 + cc;
            Br0[it] = sr[g]; Br1[it] = sr[g + Bb];
            Bi0[it] = si[g]; Bi1[it] = si[g + Bb];
        }
    };

    auto store_A_item = [&](int i, int it, int idx) {
        int kp = idx & 15, n = idx >> 4;
        char* sb = smem + slot_of(i, n >> 4) * SLOT;
        const u32 o = inner_a(n & 15, kp);
        u32 h, l;
        hilo16(Ar0[it], Ar1[it], h, l);
        *(u32*)(sb + o) = h;            *(u32*)(sb + 1024 + o) = l;
        hilo16(Ai0[it], Ai1[it], h, l);
        *(u32*)(sb + 2048 + o) = h;     *(u32*)(sb + 3072 + o) = l;
    };

    auto store_smem = [&](int i) {
        if (i <= 8) {
            #pragma unroll
            for (int it = 0; it < 8; ++it) store_A_item(i, it, tid + it * THREADS);
        } else {
            #pragma unroll
            for (int it = 0; it < 2; ++it) store_A_item(i, it, tid + it * THREADS);
        }
        char* Bp = smem + RINGB + (i & 1) * BBUF;
        #pragma unroll
        for (int it = 0; it < 4; ++it) {
            int idx = tid + it * THREADS;
            const u32 o = off_b(idx & 63, idx >> 6);
            *(u32*)(Bp + o)        = pk16(Br0[it], Br1[it]);
            *(u32*)(Bp + 4096 + o) = pk16(Bi0[it], Bi1[it]);
        }
    };

    load_regs(0);
    store_smem(0);
    __syncthreads();

    for (int i = 0; i < NTIL; ++i) {
        if (i + 1 < NTIL) load_regs(i + 1);

        const u32 s0 = smb + (u32)(slot_of(i, wr * 2) * SLOT);
        const u32 s1 = smb + (u32)(slot_of(i, wr * 2 + 1) * SLOT);
        const u32 bb = smb + RINGB + (u32)((i & 1) * BBUF);
        const u32 bn0 = (u32)(wc * 2048), bn1 = bn0 + 1024;
        #pragma unroll
        for (int ks = 0; ks < 2; ++ks) {
            const u32 ko = (u32)(ks * 512) + lane16;
            // AH/AL/BH indexed by plane p: 0=r, 1=i, 2=s(computed)
            uint4 AH[3][2], AL[3][2], BH[3][2];
            AH[0][0] = lds128(s0 + ko);         AH[0][1] = lds128(s1 + ko);
            AL[0][0] = lds128(s0 + 1024 + ko);  AL[0][1] = lds128(s1 + 1024 + ko);
            AH[1][0] = lds128(s0 + 2048 + ko);  AH[1][1] = lds128(s1 + 2048 + ko);
            AL[1][0] = lds128(s0 + 3072 + ko);  AL[1][1] = lds128(s1 + 3072 + ko);
            BH[0][0] = lds128(bb + bn0 + ko);   BH[0][1] = lds128(bb + bn1 + ko);
            BH[1][0] = lds128(bb + 4096 + bn0 + ko);
            BH[1][1] = lds128(bb + 4096 + bn1 + ko);
            #pragma unroll
            for (int mt = 0; mt < 2; ++mt)
                s2v(AH[0][mt], AL[0][mt], AH[1][mt], AL[1][mt], AH[2][mt], AL[2][mt]);
            #pragma unroll
            for (int nb = 0; nb < 2; ++nb) {
                BH[2][nb].x = h2add(BH[0][nb].x, BH[1][nb].x);
                BH[2][nb].y = h2add(BH[0][nb].y, BH[1][nb].y);
                BH[2][nb].z = h2add(BH[0][nb].z, BH[1][nb].z);
                BH[2][nb].w = h2add(BH[0][nb].w, BH[1][nb].w);
            }
            #pragma unroll
            for (int p = 0; p < 3; ++p) {
                #pragma unroll
                for (int mt = 0; mt < 2; ++mt) {
                    mma16816(acc[p][mt][0], AH[p][mt], BH[p][0].x, BH[p][0].y);
                    mma16816(acc[p][mt][0], AL[p][mt], BH[p][0].x, BH[p][0].y);
                    mma16816(acc[p][mt][1], AH[p][mt], BH[p][0].z, BH[p][0].w);
                    mma16816(acc[p][mt][1], AL[p][mt], BH[p][0].z, BH[p][0].w);
                    mma16816(acc[p][mt][2], AH[p][mt], BH[p][1].x, BH[p][1].y);
                    mma16816(acc[p][mt][2], AL[p][mt], BH[p][1].x, BH[p][1].y);
                    mma16816(acc[p][mt][3], AH[p][mt], BH[p][1].z, BH[p][1].w);
                    mma16816(acc[p][mt][3], AL[p][mt], BH[p][1].z, BH[p][1].w);
                }
            }
        }

        if (i + 1 < NTIL) store_smem(i + 1);
        __syncthreads();
    }

    // ---- epilogue: re = P1-P2, im = P3-P1-P2, soft-threshold, store ----
    const int wm = wr * 32, wn = wc * 32;
    #pragma unroll
    for (int mt = 0; mt < 2; ++mt) {
        #pragma unroll
        for (int nt = 0; nt < 4; ++nt) {
            #pragma unroll
            for (int half = 0; half < 2; ++half) {
                const int q0 = half * 2;
                const int row = row0 + wm + mt * 16 + r4 + half * 8;
                const int col = col0 + wn + nt * 8 + c2;
                float p1a = acc[0][mt][nt][q0],     p1b = acc[0][mt][nt][q0 + 1];
                float p2a = acc[1][mt][nt][q0],     p2b = acc[1][mt][nt][q0 + 1];
                float p3a = acc[2][mt][nt][q0],     p3b = acc[2][mt][nt][q0 + 1];
                float rea = p1a - p2a,  reb = p1b - p2b;
                float ima = p3a - p1a - p2a, imb = p3b - p1b - p2b;
                float maga = sqrtf(rea * rea + ima * ima);
                float sca  = fmaxf(maga - BETA, 0.0f) / fmaxf(maga, EPSL);
                float magb = sqrtf(reb * reb + imb * imb);
                float scb  = fmaxf(magb - BETA, 0.0f) / fmaxf(magb, EPSL);
                rea *= sca; ima *= sca; reb *= scb; imb *= scb;
                const int e = row * Bb + col;
                if (omode == 0) {
                    __nv_bfloat162 pa = __floats2bfloat162_rn(rea, ima);
                    __nv_bfloat162 pb = __floats2bfloat162_rn(reb, imb);
                    u32 ua, ub; memcpy(&ua, &pa, 4); memcpy(&ub, &pb, 4);
                    *(uint2*)((u32*)out + e) = make_uint2(ua, ub);
                } else {
                    *(float2*)((float*)out + e) = make_float2(rea, reb);
                }
            }
        }
    }
}

extern "C" void kernel_launch(void* const* d_in, const int* in_sizes, int n_in,
                              void* d_out, int out_size) {
    // Crash-proof input dispatch: classify by element count (elements or bytes).
    int scale = 1;
    bool have2047 = false, have8188 = false;
    for (int i = 0; i < n_in && i < 8; ++i) {
        if (in_sizes[i] == 2 * Nn - 1) have2047 = true;
        if (in_sizes[i] == (2 * Nn - 1) * 4) have8188 = true;
    }
    if (!have2047 && have8188) scale = 4;

    const float* vp[2] = {0, 0};
    const float* xp[2] = {0, 0};
    const float* mp[4] = {0, 0, 0, 0};
    int nv = 0, nx = 0, nm = 0;
    for (int i = 0; i < n_in && i < 8; ++i) {
        const float* p = (const float*)d_in[i];
        long s = in_sizes[i];
        if (s == (long)(2 * Nn - 1) * scale)      { if (nv < 2) vp[nv++] = p; }
        else if (s == (long)Nn * Bb * scale)      { if (nx < 2) xp[nx++] = p; }
        else if (s == (long)Nn * Mm * scale)      { if (nm < 4) mp[nm++] = p; }
    }
    const float* v_re  = vp[0] ? vp[0] : (const float*)d_in[0];
    const float* v_im  = vp[1] ? vp[1] : (const float*)d_in[1];
    const float* W2_re = mp[0] ? mp[0] : (const float*)d_in[2];
    const float* W2_im = mp[1] ? mp[1] : (const float*)d_in[3];
    const float* x_re  = xp[0] ? xp[0] : (const float*)d_in[4];
    const float* x_im  = xp[1] ? xp[1] : (const float*)d_in[5];
    const float* y_re  = mp[2] ? mp[2] : (const float*)d_in[6];
    const float* y_im  = mp[3] ? mp[3] : (const float*)d_in[7];

    const int omode = (out_size >= 2 * Nn * Bb) ? 0 : 1;

    cudaFuncSetAttribute(toeplitz_hmma8_kernel,
                         cudaFuncAttributeMaxDynamicSharedMemorySize, SMTOT);
    dim3 grid(Bb / TNt, Nn / TMt);   // (16, 8) = 128 CTAs
    toeplitz_hmma8_kernel<<<grid, THREADS, SMTOT>>>(
        v_re, v_im, W2_re, W2_im, x_re, x_im, y_re, y_im,
        d_out, omode);
}

// round 15
// speedup vs baseline: 1.9378x; 1.4700x over previous
#include <cuda_runtime.h>
#include <cuda_bf16.h>
#include <cuda_fp16.h>
#include <cstdint>
#include <cstring>

#define Nn 1024
#define Mm 256
#define Bb 1024
#define Kk 1280
#define TMt 128           // CTA tile rows
#define TNt 64            // CTA tile cols
#define TKt 32            // K per staged tile
#define NTIL 40           // 8 W2 tiles then 32 Toeplitz tiles
#define BETA 0.01f
#define EPSL 1e-12f
#define THREADS 256

typedef uint32_t u32;

// A ring: 16 m16-slots. Slot = 2 fp16 planes (r,i) x [ks 0..1][lane][16B]
//   slot stride 2048, plane stride 1024, ks stride 512.
// B: double buffer, 2 planes (r,i) x [n8-pair 0..3][ks][lane][16B], plane 4096.
// s-planes (r+i) are reconstructed in consumer registers.
#define SLOT 2048
#define RINGB (16 * SLOT)          // 32768
#define BBUF 8192
#define SMTOT (RINGB + 2 * BBUF)   // 49152

static __device__ __forceinline__ u32 pk16(float a, float b) {
    __half2 t = __floats2half2_rn(a, b);
    u32 h; memcpy(&h, &t, 4); return h;
}
static __device__ __forceinline__ u32 h2add(u32 a, u32 b) {
    __half2 x, y; memcpy(&x, &a, 4); memcpy(&y, &b, 4);
    __half2 r = __hadd2(x, y); u32 d; memcpy(&d, &r, 4); return d;
}
static __device__ __forceinline__ uint4 h2add4(const uint4& a, const uint4& b) {
    uint4 r;
    r.x = h2add(a.x, b.x); r.y = h2add(a.y, b.y);
    r.z = h2add(a.z, b.z); r.w = h2add(a.w, b.w);
    return r;
}
static __device__ __forceinline__ u32 smem_u32(const void* p) {
    u32 a;
    asm("{ .reg .u64 t; cvta.to.shared.u64 t, %1; cvt.u32.u64 %0, t; }" : "=r"(a) : "l"(p));
    return a;
}
static __device__ __forceinline__ uint4 lds128(u32 addr) {
    uint4 r;
    asm volatile("ld.shared.v4.b32 {%0,%1,%2,%3}, [%4];"
                 : "=r"(r.x), "=r"(r.y), "=r"(r.z), "=r"(r.w) : "r"(addr));
    return r;
}
static __device__ __forceinline__ void mma16816(float* c, const uint4& a, u32 b0, u32 b1) {
    asm volatile(
        "mma.sync.aligned.m16n8k16.row.col.f32.f16.f16.f32 "
        "{%0,%1,%2,%3}, {%4,%5,%6,%7}, {%8,%9}, {%0,%1,%2,%3};"
        : "+f"(c[0]), "+f"(c[1]), "+f"(c[2]), "+f"(c[3])
        : "r"(a.x), "r"(a.y), "r"(a.z), "r"(a.w), "r"(b0), "r"(b1));
}

// k0 of schedule index i: W2 region first (i<8), then Toeplitz ascending.
static __device__ __forceinline__ int k0_of(int i) {
    return (i < 8) ? (1024 + i * 32) : ((i - 8) * 32);
}
// ring slot of m16-tile j for schedule index i
static __device__ __forceinline__ int slot_of(int i, int j) {
    return (i < 8) ? (8 * (i & 1) + j) : ((j - 2 * (i - 8)) & 15);
}
// within-(slot,plane) offset for value (nl in 0..15, kp in 0..15)  [proven map]
static __device__ __forceinline__ u32 inner_a(int nl, int kp) {
    int kpp = kp & 7;
    return (u32)((kp >> 3) * 512 + (((nl & 7) * 4 + (kpp & 3)) * 16) +
                 (((kpp >= 4) ? 2 : 0) + (nl >> 3)) * 4);
}
// within-plane offset for B value (c in 0..63, kp in 0..15)  [proven map]
static __device__ __forceinline__ u32 off_b(int c, int kp) {
    int kpp = kp & 7;
    return (u32)((c >> 4) * 1024 + (kp >> 3) * 512 +
                 (((c & 7) * 4 + (kpp & 3)) * 16) +
                 ((((c >> 3) & 1) * 2) + ((kpp >= 4) ? 1 : 0)) * 4);
}

// z = softthresh(W1 @ x + W2 @ y); W1[n,k]=v[N-1+n-k].
// Plain fp16 A and B + Gauss 3-product (3 MMA/k-step); A-ring; reg s-planes.
__global__ __launch_bounds__(THREADS, 1)
void toeplitz_hmma9_kernel(
    const float* __restrict__ v_re,  const float* __restrict__ v_im,
    const float* __restrict__ W2_re, const float* __restrict__ W2_im,
    const float* __restrict__ x_re,  const float* __restrict__ x_im,
    const float* __restrict__ y_re,  const float* __restrict__ y_im,
    void* __restrict__ out, int omode)
{
    extern __shared__ char smem[];
    const u32 smb = smem_u32(smem);
    const int tid = threadIdx.x;
    const int wid = tid >> 5;
    const int lid = tid & 31;
    const int wr = wid >> 1, wc = wid & 1;    // 4x2 warp grid, warp tile 32x32
    const int r4 = lid >> 2;
    const int c2 = (lid & 3) * 2;
    const int row0 = blockIdx.y * TMt;
    const int col0 = blockIdx.x * TNt;
    const u32 lane16 = (u32)(lid * 16);

    float acc[3][2][4][4];
    #pragma unroll
    for (int p = 0; p < 3; ++p)
        #pragma unroll
        for (int mt = 0; mt < 2; ++mt)
            #pragma unroll
            for (int nt = 0; nt < 4; ++nt)
                #pragma unroll
                for (int q = 0; q < 4; ++q) acc[p][mt][nt][q] = 0.0f;

    float Ar0[8], Ar1[8], Ai0[8], Ai1[8];
    float Br0[4], Br1[4], Bi0[4], Bi1[4];

    auto load_regs = [&](int i) {
        const int k0 = k0_of(i);
        const bool fullA = (i <= 8);
        if (fullA) {
            if (i < 8) {
                #pragma unroll
                for (int it = 0; it < 8; ++it) {
                    int idx = tid + it * THREADS;     // 0..2047
                    int kp = idx & 15, n = idx >> 4;
                    int g = (row0 + n) * Mm + (k0 - Nn + 2 * kp);
                    Ar0[it] = W2_re[g]; Ar1[it] = W2_re[g + 1];
                    Ai0[it] = W2_im[g]; Ai1[it] = W2_im[g + 1];
                }
            } else {
                #pragma unroll
                for (int it = 0; it < 8; ++it) {
                    int idx = tid + it * THREADS;
                    int kp = idx & 15, n = idx >> 4;
                    int g = 1023 + (row0 + n) - (k0 + 2 * kp);
                    Ar0[it] = v_re[g]; Ar1[it] = v_re[g - 1];
                    Ai0[it] = v_im[g]; Ai1[it] = v_im[g - 1];
                }
            }
        } else {
            #pragma unroll
            for (int it = 0; it < 2; ++it) {
                int idx = tid + it * THREADS;         // 0..511, n in 0..31
                int kp = idx & 15, n = idx >> 4;
                int g = 1023 + (row0 + n) - (k0 + 2 * kp);
                Ar0[it] = v_re[g]; Ar1[it] = v_re[g - 1];
                Ai0[it] = v_im[g]; Ai1[it] = v_im[g - 1];
            }
        }
        const float* sr = (k0 < Nn) ? x_re : y_re;
        const float* si = (k0 < Nn) ? x_im : y_im;
        const int kb = (k0 < Nn) ? k0 : (k0 - Nn);
        #pragma unroll
        for (int it = 0; it < 4; ++it) {
            int idx = tid + it * THREADS;             // 0..1023
            int cc = idx & 63, kp = idx >> 6;
            int g = (kb + 2 * kp) * Bb + col0 + cc;
            Br0[it] = sr[g]; Br1[it] = sr[g + Bb];
            Bi0[it] = si[g]; Bi1[it] = si[g + Bb];
        }
    };

    auto store_A_item = [&](int i, int it, int idx) {
        int kp = idx & 15, n = idx >> 4;
        char* sb = smem + slot_of(i, n >> 4) * SLOT;
        const u32 o = inner_a(n & 15, kp);
        *(u32*)(sb + o)        = pk16(Ar0[it], Ar1[it]);
        *(u32*)(sb + 1024 + o) = pk16(Ai0[it], Ai1[it]);
    };

    auto store_smem = [&](int i) {
        if (i <= 8) {
            #pragma unroll
            for (int it = 0; it < 8; ++it) store_A_item(i, it, tid + it * THREADS);
        } else {
            #pragma unroll
            for (int it = 0; it < 2; ++it) store_A_item(i, it, tid + it * THREADS);
        }
        char* Bp = smem + RINGB + (i & 1) * BBUF;
        #pragma unroll
        for (int it = 0; it < 4; ++it) {
            int idx = tid + it * THREADS;
            const u32 o = off_b(idx & 63, idx >> 6);
            *(u32*)(Bp + o)        = pk16(Br0[it], Br1[it]);
            *(u32*)(Bp + 4096 + o) = pk16(Bi0[it], Bi1[it]);
        }
    };

    load_regs(0);
    store_smem(0);
    __syncthreads();

    for (int i = 0; i < NTIL; ++i) {
        if (i + 1 < NTIL) load_regs(i + 1);

        const u32 s0 = smb + (u32)(slot_of(i, wr * 2) * SLOT);
        const u32 s1 = smb + (u32)(slot_of(i, wr * 2 + 1) * SLOT);
        const u32 bb = smb + RINGB + (u32)((i & 1) * BBUF);
        const u32 bn0 = (u32)(wc * 2048), bn1 = bn0 + 1024;
        #pragma unroll
        for (int ks = 0; ks < 2; ++ks) {
            const u32 ko = (u32)(ks * 512) + lane16;
            // planes p: 0=r, 1=i, 2=s(computed in regs)
            uint4 AH[3][2], BH[3][2];
            AH[0][0] = lds128(s0 + ko);         AH[0][1] = lds128(s1 + ko);
            AH[1][0] = lds128(s0 + 1024 + ko);  AH[1][1] = lds128(s1 + 1024 + ko);
            BH[0][0] = lds128(bb + bn0 + ko);   BH[0][1] = lds128(bb + bn1 + ko);
            BH[1][0] = lds128(bb + 4096 + bn0 + ko);
            BH[1][1] = lds128(bb + 4096 + bn1 + ko);
            #pragma unroll
            for (int mt = 0; mt < 2; ++mt) AH[2][mt] = h2add4(AH[0][mt], AH[1][mt]);
            #pragma unroll
            for (int nb = 0; nb < 2; ++nb) BH[2][nb] = h2add4(BH[0][nb], BH[1][nb]);
            #pragma unroll
            for (int p = 0; p < 3; ++p) {
                #pragma unroll
                for (int mt = 0; mt < 2; ++mt) {
                    mma16816(acc[p][mt][0], AH[p][mt], BH[p][0].x, BH[p][0].y);
                    mma16816(acc[p][mt][1], AH[p][mt], BH[p][0].z, BH[p][0].w);
                    mma16816(acc[p][mt][2], AH[p][mt], BH[p][1].x, BH[p][1].y);
                    mma16816(acc[p][mt][3], AH[p][mt], BH[p][1].z, BH[p][1].w);
                }
            }
        }

        if (i + 1 < NTIL) store_smem(i + 1);
        __syncthreads();
    }

    // ---- epilogue: re = P1-P2, im = P3-P1-P2, soft-threshold, store ----
    const int wm = wr * 32, wn = wc * 32;
    #pragma unroll
    for (int mt = 0; mt < 2; ++mt) {
        #pragma unroll
        for (int nt = 0; nt < 4; ++nt) {
            #pragma unroll
            for (int half = 0; half < 2; ++half) {
                const int q0 = half * 2;
                const int row = row0 + wm + mt * 16 + r4 + half * 8;
                const int col = col0 + wn + nt * 8 + c2;
                float p1a = acc[0][mt][nt][q0],     p1b = acc[0][mt][nt][q0 + 1];
                float p2a = acc[1][mt][nt][q0],     p2b = acc[1][mt][nt][q0 + 1];
                float p3a = acc[2][mt][nt][q0],     p3b = acc[2][mt][nt][q0 + 1];
                float rea = p1a - p2a,  reb = p1b - p2b;
                float ima = p3a - p1a - p2a, imb = p3b - p1b - p2b;
                float maga = sqrtf(rea * rea + ima * ima);
                float sca  = fmaxf(maga - BETA, 0.0f) / fmaxf(maga, EPSL);
                float magb = sqrtf(reb * reb + imb * imb);
                float scb  = fmaxf(magb - BETA, 0.0f) / fmaxf(magb, EPSL);
                rea *= sca; ima *= sca; reb *= scb; imb *= scb;
                const int e = row * Bb + col;
                if (omode == 0) {
                    __nv_bfloat162 pa = __floats2bfloat162_rn(rea, ima);
                    __nv_bfloat162 pb = __floats2bfloat162_rn(reb, imb);
                    u32 ua, ub; memcpy(&ua, &pa, 4); memcpy(&ub, &pb, 4);
                    *(uint2*)((u32*)out + e) = make_uint2(ua, ub);
                } else {
                    *(float2*)((float*)out + e) = make_float2(rea, reb);
                }
            }
        }
    }
}

extern "C" void kernel_launch(void* const* d_in, const int* in_sizes, int n_in,
                              void* d_out, int out_size) {
    // Crash-proof input dispatch: classify by element count (elements or bytes).
    int scale = 1;
    bool have2047 = false, have8188 = false;
    for (int i = 0; i < n_in && i < 8; ++i) {
        if (in_sizes[i] == 2 * Nn - 1) have2047 = true;
        if (in_sizes[i] == (2 * Nn - 1) * 4) have8188 = true;
    }
    if (!have2047 && have8188) scale = 4;

    const float* vp[2] = {0, 0};
    const float* xp[2] = {0, 0};
    const float* mp[4] = {0, 0, 0, 0};
    int nv = 0, nx = 0, nm = 0;
    for (int i = 0; i < n_in && i < 8; ++i) {
        const float* p = (const float*)d_in[i];
        long s = in_sizes[i];
        if (s == (long)(2 * Nn - 1) * scale)      { if (nv < 2) vp[nv++] = p; }
        else if (s == (long)Nn * Bb * scale)      { if (nx < 2) xp[nx++] = p; }
        else if (s == (long)Nn * Mm * scale)      { if (nm < 4) mp[nm++] = p; }
    }
    const float* v_re  = vp[0] ? vp[0] : (const float*)d_in[0];
    const float* v_im  = vp[1] ? vp[1] : (const float*)d_in[1];
    const float* W2_re = mp[0] ? mp[0] : (const float*)d_in[2];
    const float* W2_im = mp[1] ? mp[1] : (const float*)d_in[3];
    const float* x_re  = xp[0] ? xp[0] : (const float*)d_in[4];
    const float* x_im  = xp[1] ? xp[1] : (const float*)d_in[5];
    const float* y_re  = mp[2] ? mp[2] : (const float*)d_in[6];
    const float* y_im  = mp[3] ? mp[3] : (const float*)d_in[7];

    const int omode = (out_size >= 2 * Nn * Bb) ? 0 : 1;

    cudaFuncSetAttribute(toeplitz_hmma9_kernel,
                         cudaFuncAttributeMaxDynamicSharedMemorySize, SMTOT);
    dim3 grid(Bb / TNt, Nn / TMt);   // (16, 8) = 128 CTAs
    toeplitz_hmma9_kernel<<<grid, THREADS, SMTOT>>>(
        v_re, v_im, W2_re, W2_im, x_re, x_im, y_re, y_im,
        d_out, omode);
}